// round 15
// baseline (speedup 1.0000x reference)
#include <cuda_runtime.h>
#include <cuda_bf16.h>
#include <cuda_fp16.h>
#include <math_constants.h>
#include <cstdint>

#define BATCH 2
#define CH    128
#define NSP   4096
#define GROUPS 8
#define TN    64
#define EPSV  1e-5f

// attention tiling
#define TQ     128
#define TKK    64
#define KSPLIT 2
#define NT2    (NSP/KSPLIT/TKK)   // 32

// ---------------- scratch (static __device__, allocation-free) ----------------
__device__ uint32_t g_Q16[BATCH*NSP*64];      // [b][n][cw] fp16x2
__device__ uint32_t g_K16[BATCH*NSP*64];      // [b][m][cw] fp16x2
__device__ uint32_t g_V16[BATCH*NSP*64];      // [b][m][cw] fp16x2 (row-major V)
__device__ float g_Op[KSPLIT*BATCH*NSP*CH];   // unnormalized O  [s][b][n][c]
__device__ float g_lp[KSPLIT*BATCH*NSP];      // exp-sums        [s][b][n]
__device__ float g_mx[KSPLIT*BATCH*NSP];      // row maxes       [s][b][n]
__device__ float g_Y [BATCH*CH*NSP];
__device__ float g_part [BATCH*64*GROUPS*2];

// ---------------- f32x2 helpers ----------------
__device__ __forceinline__ unsigned long long pk2(float x, float y){
    unsigned long long r; asm("mov.b64 %0, {%1,%2};" : "=l"(r) : "f"(x), "f"(y)); return r;
}
__device__ __forceinline__ void upk2(unsigned long long v, float& x, float& y){
    asm("mov.b64 {%0,%1}, %2;" : "=f"(x), "=f"(y) : "l"(v));
}
__device__ __forceinline__ void ffma2(unsigned long long& d, unsigned long long a, unsigned long long b){
    asm("fma.rn.f32x2 %0, %1, %2, %0;" : "+l"(d) : "l"(a), "l"(b));
}

// ---------------- smem / mma / ldmatrix / cp.async helpers ----------------
__device__ __forceinline__ uint32_t smem_u32(const void* p){
    uint32_t a;
    asm("{ .reg .u64 t; cvta.to.shared.u64 t, %1; cvt.u32.u64 %0, t; }" : "=r"(a) : "l"(p));
    return a;
}
__device__ __forceinline__ void cpa(uint32_t saddr, const void* g){
    asm volatile("cp.async.ca.shared.global [%0], [%1], 16;" :: "r"(saddr), "l"(g) : "memory");
}
#define CPA_COMMIT() asm volatile("cp.async.commit_group;" ::: "memory")
#define CPA_WAIT0()  asm volatile("cp.async.wait_group 0;" ::: "memory")
#define CPA_WAIT2()  asm volatile("cp.async.wait_group 2;" ::: "memory")
#define CPA_WAIT3()  asm volatile("cp.async.wait_group 3;" ::: "memory")

__device__ __forceinline__ void ldsm4(uint32_t a, uint32_t r[4]){
    asm volatile("ldmatrix.sync.aligned.m8n8.x4.shared.b16 {%0,%1,%2,%3}, [%4];"
      : "=r"(r[0]), "=r"(r[1]), "=r"(r[2]), "=r"(r[3]) : "r"(a));
}
__device__ __forceinline__ void ldsm4t(uint32_t a, uint32_t r[4]){
    asm volatile("ldmatrix.sync.aligned.m8n8.x4.trans.shared.b16 {%0,%1,%2,%3}, [%4];"
      : "=r"(r[0]), "=r"(r[1]), "=r"(r[2]), "=r"(r[3]) : "r"(a));
}
// fp16 mma
__device__ __forceinline__ void mmah(float c[4], const uint32_t a[4], const uint32_t b[2]){
    asm volatile("mma.sync.aligned.m16n8k16.row.col.f32.f16.f16.f32 "
      "{%0,%1,%2,%3}, {%4,%5,%6,%7}, {%8,%9}, {%0,%1,%2,%3};"
      : "+f"(c[0]), "+f"(c[1]), "+f"(c[2]), "+f"(c[3])
      : "r"(a[0]), "r"(a[1]), "r"(a[2]), "r"(a[3]), "r"(b[0]), "r"(b[1]));
}

// single fp16 pack of a float pair
__device__ __forceinline__ uint32_t packh2(float a, float b){
    __half2 h = __floats2half2_rn(a, b);
    return *reinterpret_cast<uint32_t*>(&h);
}

// smem byte offsets for k_attn (row stride 272B everywhere)
// Q: 128 rows.  K bufs: 64 rows x2.  V bufs: 64 rows x2.
#define QS   0
#define KB0  34816
#define KBSZ 17408
#define VB0  69632
#define VBSZ 17408
#define SM_ATTN 104448

// ============================================================================
// K1: Q/K/V projections (fp32 scalar), direct register->global fp16 stores.
// All three -> single fp16 [b][row][c].
// ============================================================================
__global__ __launch_bounds__(256) void k_qkv(const float* __restrict__ x,
                                             const float* __restrict__ Wq,
                                             const float* __restrict__ Wk,
                                             const float* __restrict__ Wv)
{
    extern __shared__ float sm[];
    float* Wt = sm;               // [c][130]
    float* Xs = sm + 128*130;     // [c][64]

    const int n0  = blockIdx.x * TN;
    const int b   = blockIdx.y;
    const int z   = blockIdx.z;
    const float* W = (z == 0) ? Wq : ((z == 1) ? Wk : Wv);

    const int tid = threadIdx.x;
    const int tx  = tid & 15;
    const int ty  = tid >> 4;

    for (int idx = tid; idx < 128*64; idx += 256){
        int o  = idx >> 6;
        int cq = (idx & 63) << 1;
        float2 w = *(const float2*)(W + o*128 + cq);
        Wt[ cq   *130 + o] = w.x;
        Wt[(cq+1)*130 + o] = w.y;
    }
    const float* xb = x + (size_t)b*CH*NSP + n0;
    for (int idx = tid; idx < 128*16; idx += 256){
        int c = idx >> 4, u = (idx & 15) << 2;
        *(float4*)(Xs + c*64 + u) = *(const float4*)(xb + c*NSP + u);
    }
    __syncthreads();

    unsigned long long acc[4][4];
    #pragma unroll
    for (int i = 0; i < 4; i++)
        #pragma unroll
        for (int j = 0; j < 4; j++) acc[i][j] = 0ull;

    #pragma unroll 4
    for (int c = 0; c < 128; c++){
        unsigned long long wv[4]; float xn[4];
        #pragma unroll
        for (int j = 0; j < 4; j++)
            wv[j] = *(const unsigned long long*)(Wt + c*130 + 2*tx + 32*j);
        #pragma unroll
        for (int i = 0; i < 4; i++) xn[i] = Xs[c*64 + ty + 16*i];
        #pragma unroll
        for (int i = 0; i < 4; i++){
            unsigned long long xd = pk2(xn[i], xn[i]);
            #pragma unroll
            for (int j = 0; j < 4; j++) ffma2(acc[i][j], wv[j], xd);
        }
    }

    // direct stores: thread holds (o, o+1) pair = one fp16x2 word at [n][cw]
    uint32_t* ok = (z == 0 ? g_Q16 : (z == 1 ? g_K16 : g_V16)) + ((size_t)b*NSP + n0)*64;
    #pragma unroll
    for (int i = 0; i < 4; i++)
        #pragma unroll
        for (int j = 0; j < 4; j++){
            float a, bv; upk2(acc[i][j], a, bv);
            int n = ty + 16*i, cw = tx + 16*j;
            ok[n*64 + cw] = packh2(a, bv);
        }
}

// ============================================================================
// K2: HMMA flash attention, online softmax, split-K, SOFTWARE-PIPELINED:
// QK(t+1) overlaps the exp/softmax of tile t (double-buffered sacc).
// Ladder: prologue {Q,K0},{K1},{V0}; per tile commit {K(t+2)},{V(t+1)}.
// Waits: wait3 -> K(t+1) ready (before QK(t+1)); wait2 -> V(t) ready (before PV).
// ============================================================================
__global__ __launch_bounds__(256) void k_attn()
{
    extern __shared__ char smc[];
    const uint32_t sb = smem_u32(smc);
    const int tid = threadIdx.x;
    const int wid = tid >> 5, lane = tid & 31;
    const int n0 = blockIdx.x * TQ;
    const int b  = blockIdx.y;
    const int sp = blockIdx.z;
    const int m_base = sp * (NSP/KSPLIT);

    const uint32_t* Q16 = g_Q16 + ((size_t)b*NSP + n0)*64;
    const uint32_t* K16 = g_K16 + (size_t)b*NSP*64;
    const uint32_t* V16 = g_V16 + (size_t)b*NSP*64;

    // ---- prologue: G0={Q,K0}, G1={K1}, G2={V0} ----
    for (int i = tid; i < 2048; i += 256){
        int r = i >> 4, q = i & 15;
        cpa(sb + QS + (uint32_t)r*272 + q*16, Q16 + r*64 + q*4);
    }
    for (int i = tid; i < 1024; i += 256){
        int r = i >> 4, q = i & 15;
        cpa(sb + KB0 + (uint32_t)r*272 + q*16, K16 + (size_t)(m_base + r)*64 + q*4);
    }
    CPA_COMMIT();
    for (int i = tid; i < 1024; i += 256){
        int r = i >> 4, q = i & 15;
        cpa(sb + KB0 + KBSZ + (uint32_t)r*272 + q*16, K16 + (size_t)(m_base + TKK + r)*64 + q*4);
    }
    CPA_COMMIT();
    for (int i = tid; i < 1024; i += 256){
        int r = i >> 4, q = i & 15;
        cpa(sb + VB0 + (uint32_t)r*272 + q*16, V16 + (size_t)(m_base + r)*64 + q*4);
    }
    CPA_COMMIT();
    CPA_WAIT2();            // Q + K0 ready
    __syncthreads();

    // fragment address bases (row stride 272B everywhere)
    const int arow = 16*wid + (lane & 7) + ((lane >> 3) & 1)*8;
    const uint32_t aoff = (uint32_t)arow*272 + ((lane >> 4) & 1)*16;
    const int brow = (lane & 7) + ((lane >> 4) & 1)*8;
    const uint32_t boff = ((lane >> 3) & 1)*16;
    const int vrow = (lane & 7) + ((lane >> 3) & 1)*8;
    const uint32_t voff = ((lane >> 4) & 1)*16;

    // ---- cache Q A-fragments for the whole kernel ----
    uint32_t qf[8][4];
    #pragma unroll
    for (int k = 0; k < 8; k++) ldsm4(sb + QS + aoff + k*32, qf[k]);

    float oacc[16][4];
    #pragma unroll
    for (int i = 0; i < 16; i++)
        #pragma unroll
        for (int j = 0; j < 4; j++) oacc[i][j] = 0.f;
    float lsum0 = 0.f, lsum1 = 0.f;
    float mrow0 = -CUDART_INF_F, mrow1 = -CUDART_INF_F;

    float sacc[2][8][4];

    // ---- QK(0) into sacc[0] ----
    #pragma unroll
    for (int i = 0; i < 8; i++)
        #pragma unroll
        for (int j = 0; j < 4; j++) sacc[0][i][j] = 0.f;
    #pragma unroll
    for (int k = 0; k < 8; k++){
        #pragma unroll
        for (int jj = 0; jj < 4; jj++){
            uint32_t bh[4];
            uint32_t ro = (uint32_t)(16*jj + brow)*272 + boff + k*32;
            ldsm4(sb + KB0 + ro, bh);
            mmah(sacc[0][2*jj],     qf[k], bh);
            mmah(sacc[0][2*jj + 1], qf[k], bh + 2);
        }
    }

    for (int t = 0; t < NT2; t++){
        const int cur = t & 1, nxt = cur ^ 1;
        const uint32_t vb = sb + VB0 + (uint32_t)cur*VBSZ;

        // barrier: all warps done QK(t) [iter t-1 or prologue] and PV(t-1)
        __syncthreads();

        // commit K(t+2) into kbuf[t&1] (empty group if out of range)
        if (t + 2 < NT2){
            const int m2 = m_base + (t + 2)*TKK;
            const uint32_t kn = sb + KB0 + (uint32_t)cur*KBSZ;
            for (int i = tid; i < 1024; i += 256){
                int r = i >> 4, q = i & 15;
                cpa(kn + (uint32_t)r*272 + q*16, K16 + (size_t)(m2 + r)*64 + q*4);
            }
        }
        CPA_COMMIT();
        // commit V(t+1) into vbuf[(t+1)&1] (empty group if out of range)
        if (t + 1 < NT2){
            const int m1 = m_base + (t + 1)*TKK;
            const uint32_t vn = sb + VB0 + (uint32_t)nxt*VBSZ;
            for (int i = tid; i < 1024; i += 256){
                int r = i >> 4, q = i & 15;
                cpa(vn + (uint32_t)r*272 + q*16, V16 + (size_t)(m1 + r)*64 + q*4);
            }
        }
        CPA_COMMIT();

        // ---- QK(t+1) into sacc[nxt] (overlaps the exp phase below) ----
        if (t + 1 < NT2){
            CPA_WAIT3();            // K(t+1) landed
            const uint32_t kb = sb + KB0 + (uint32_t)nxt*KBSZ;
            #pragma unroll
            for (int i = 0; i < 8; i++)
                #pragma unroll
                for (int j = 0; j < 4; j++) sacc[nxt][i][j] = 0.f;
            #pragma unroll
            for (int k = 0; k < 8; k++){
                #pragma unroll
                for (int jj = 0; jj < 4; jj++){
                    uint32_t bh[4];
                    uint32_t ro = (uint32_t)(16*jj + brow)*272 + boff + k*32;
                    ldsm4(kb + ro, bh);
                    mmah(sacc[nxt][2*jj],     qf[k], bh);
                    mmah(sacc[nxt][2*jj + 1], qf[k], bh + 2);
                }
            }
        }

        // ---- online row max + exp on sacc[cur] (MUFU/ALU; tensor pipe busy) ----
        float tm0 = sacc[cur][0][0], tm1 = sacc[cur][0][2];
        #pragma unroll
        for (int j = 0; j < 8; j++){
            tm0 = fmaxf(tm0, fmaxf(sacc[cur][j][0], sacc[cur][j][1]));
            tm1 = fmaxf(tm1, fmaxf(sacc[cur][j][2], sacc[cur][j][3]));
        }
        #pragma unroll
        for (int d = 1; d < 4; d <<= 1){
            tm0 = fmaxf(tm0, __shfl_xor_sync(0xffffffffu, tm0, d));
            tm1 = fmaxf(tm1, __shfl_xor_sync(0xffffffffu, tm1, d));
        }
        float mn0 = fmaxf(mrow0, tm0), mn1 = fmaxf(mrow1, tm1);
        float sc0 = __expf(mrow0 - mn0), sc1 = __expf(mrow1 - mn1);
        mrow0 = mn0; mrow1 = mn1;
        if (!__all_sync(0xffffffffu, (sc0 == 1.0f) && (sc1 == 1.0f))){
            #pragma unroll
            for (int i = 0; i < 16; i++){
                oacc[i][0] *= sc0; oacc[i][1] *= sc0;
                oacc[i][2] *= sc1; oacc[i][3] *= sc1;
            }
            lsum0 *= sc0; lsum1 *= sc1;
        }

        uint32_t pf[4][4];
        #pragma unroll
        for (int j = 0; j < 8; j++){
            float p0 = __expf(sacc[cur][j][0] - mn0);
            float p1 = __expf(sacc[cur][j][1] - mn0);
            float p2 = __expf(sacc[cur][j][2] - mn1);
            float p3 = __expf(sacc[cur][j][3] - mn1);
            lsum0 += p0 + p1; lsum1 += p2 + p3;
            int jk = j >> 1, hv = (j & 1) << 1;
            pf[jk][hv]     = packh2(p0, p1);
            pf[jk][hv + 1] = packh2(p2, p3);
        }

        // ---- V(t) ready, then PV(t) ----
        CPA_WAIT2();
        #pragma unroll
        for (int k = 0; k < 4; k++){
            #pragma unroll
            for (int jj = 0; jj < 8; jj++){
                uint32_t bh[4];
                uint32_t ro = (uint32_t)(16*k + vrow)*272 + voff + jj*32;
                ldsm4t(vb + ro, bh);
                mmah(oacc[2*jj],     pf[k], bh);
                mmah(oacc[2*jj + 1], pf[k], bh + 2);
            }
        }
    }

    // ---- epilogue: l and m per row, unnormalized (max-relative) O out ----
    #pragma unroll
    for (int d = 1; d < 4; d <<= 1){
        lsum0 += __shfl_xor_sync(0xffffffffu, lsum0, d);
        lsum1 += __shfl_xor_sync(0xffffffffu, lsum1, d);
    }
    const int g = lane >> 2, q = lane & 3;
    const int row = 16*wid + g;
    if (q == 0){
        size_t lb = ((size_t)sp*BATCH + b)*NSP + n0;
        g_lp[lb + row]     = lsum0;
        g_lp[lb + row + 8] = lsum1;
        g_mx[lb + row]     = mrow0;
        g_mx[lb + row + 8] = mrow1;
    }
    float* Ob = g_Op + (((size_t)sp*BATCH + b)*NSP + n0)*CH;
    #pragma unroll
    for (int tt = 0; tt < 16; tt++){
        int c = 8*tt + 2*q;
        *(float2*)(Ob + (size_t)row*CH + c)       = make_float2(oacc[tt][0], oacc[tt][1]);
        *(float2*)(Ob + (size_t)(row + 8)*CH + c) = make_float2(oacc[tt][2], oacc[tt][3]);
    }
}

// ============================================================================
// K3: combine splits (m/l merge), y = x + Wo @ h, per-(b,group) partials.
// ============================================================================
__global__ __launch_bounds__(256) void k_proj(const float* __restrict__ x,
                                              const float* __restrict__ Wo)
{
    extern __shared__ float sm[];
    __shared__ float w0S[64], w1S[64];
    float* Wt = sm;               // [c][130]
    float* HS = sm + 128*130;     // [n][129] compute; [o][65] staging

    const int n0 = blockIdx.x * TN;
    const int b  = blockIdx.y;
    const int tid = threadIdx.x;
    const int tx  = tid & 15;
    const int ty  = tid >> 4;

    if (tid < 64){
        size_t i0 = ((size_t)0*BATCH + b)*NSP + n0 + tid;
        size_t i1 = ((size_t)1*BATCH + b)*NSP + n0 + tid;
        float l0 = g_lp[i0], l1 = g_lp[i1];
        float m0 = g_mx[i0], m1 = g_mx[i1];
        float M  = fmaxf(m0, m1);
        float e0 = __expf(m0 - M), e1 = __expf(m1 - M);
        float rl = 1.0f / (l0*e0 + l1*e1);
        w0S[tid] = e0 * rl;
        w1S[tid] = e1 * rl;
    }
    for (int idx = tid; idx < 128*64; idx += 256){
        int o  = idx >> 6;
        int cq = (idx & 63) << 1;
        float2 w = *(const float2*)(Wo + o*128 + cq);
        Wt[ cq   *130 + o] = w.x;
        Wt[(cq+1)*130 + o] = w.y;
    }
    __syncthreads();

    const float* O0 = g_Op + (((size_t)0*BATCH + b)*NSP + n0)*CH;
    const float* O1 = g_Op + (((size_t)1*BATCH + b)*NSP + n0)*CH;
    for (int idx = tid; idx < 64*128; idx += 256){
        int n = idx >> 7, c = idx & 127;
        HS[n*129 + c] = O0[idx]*w0S[n] + O1[idx]*w1S[n];
    }
    __syncthreads();

    unsigned long long acc[4][4];
    #pragma unroll
    for (int i = 0; i < 4; i++)
        #pragma unroll
        for (int j = 0; j < 4; j++) acc[i][j] = 0ull;

    #pragma unroll 4
    for (int c = 0; c < 128; c++){
        unsigned long long wv[4]; float hv[4];
        #pragma unroll
        for (int j = 0; j < 4; j++)
            wv[j] = *(const unsigned long long*)(Wt + c*130 + 2*tx + 32*j);
        #pragma unroll
        for (int i = 0; i < 4; i++) hv[i] = HS[(ty + 16*i)*129 + c];
        #pragma unroll
        for (int i = 0; i < 4; i++){
            unsigned long long hd = pk2(hv[i], hv[i]);
            #pragma unroll
            for (int j = 0; j < 4; j++) ffma2(acc[i][j], wv[j], hd);
        }
    }
    __syncthreads();

    float* St = HS;  // [o][65]
    #pragma unroll
    for (int i = 0; i < 4; i++)
        #pragma unroll
        for (int j = 0; j < 4; j++){
            float a, bv; upk2(acc[i][j], a, bv);
            int o = 2*tx + 32*j, n = ty + 16*i;
            St[ o   *65 + n] = a;
            St[(o+1)*65 + n] = bv;
        }
    __syncthreads();

    const float* xb = x   + (size_t)b*CH*NSP + n0;
    float*       yb = g_Y + (size_t)b*CH*NSP + n0;
    const int w = tid >> 5, lane = tid & 31;
    float s1 = 0.f, s2 = 0.f;
    for (int k = 0; k < 32; k++){
        int e = w*1024 + k*32 + lane;
        int o = e >> 6, n = e & 63;
        float val = xb[o*NSP + n] + St[o*65 + n];
        yb[o*NSP + n] = val;
        s1 += val; s2 += val*val;
    }
    #pragma unroll
    for (int d = 16; d >= 1; d >>= 1){
        s1 += __shfl_xor_sync(0xffffffffu, s1, d);
        s2 += __shfl_xor_sync(0xffffffffu, s2, d);
    }
    if (lane == 0){
        float* p = g_part + ((size_t)(b*64 + blockIdx.x)*GROUPS + w)*2;
        p[0] = s1; p[1] = s2;
    }
}

// K4: GroupNorm + affine + SiLU, with fused (redundant, deterministic)
// per-block reduction of the 64 partial sums for this block's group.
__global__ __launch_bounds__(256) void k_norm(const float* __restrict__ gamma,
                                              const float* __restrict__ beta,
                                              float* __restrict__ out)
{
    __shared__ float sh_mean, sh_inv;
    const int tid = threadIdx.x;
    const int e0 = blockIdx.x << 10;        // 1024 elems per block
    const int b = e0 >> 19;
    const int c = (e0 >> 12) & 127;
    const int g = c >> 4;

    if (tid < 32){
        const float* p = g_part + ((size_t)(b*64)*GROUPS + g)*2;
        float s1 = p[(size_t)tid*GROUPS*2]     + p[(size_t)(tid+32)*GROUPS*2];
        float s2 = p[(size_t)tid*GROUPS*2 + 1] + p[(size_t)(tid+32)*GROUPS*2 + 1];
        #pragma unroll
        for (int d = 16; d >= 1; d >>= 1){
            s1 += __shfl_xor_sync(0xffffffffu, s1, d);
            s2 += __shfl_xor_sync(0xffffffffu, s2, d);
        }
        if (tid == 0){
            const float icnt = 1.0f / 65536.0f;
            float mean = s1 * icnt;
            float var  = s2 * icnt - mean*mean;
            sh_mean = mean;
            sh_inv  = rsqrtf(var + EPSV);
        }
    }
    __syncthreads();

    const float mean = sh_mean, inv = sh_inv;
    const float ga = gamma[c], be = beta[c];
    const int e = e0 + tid*4;
    float4 y = *(const float4*)(g_Y + e);
    float4 r;
    float t = (y.x - mean)*inv*ga + be; r.x = t / (1.0f + __expf(-t));
    t = (y.y - mean)*inv*ga + be;       r.y = t / (1.0f + __expf(-t));
    t = (y.z - mean)*inv*ga + be;       r.z = t / (1.0f + __expf(-t));
    t = (y.w - mean)*inv*ga + be;       r.w = t / (1.0f + __expf(-t));
    *(float4*)(out + e) = r;
}

// ============================================================================
extern "C" void kernel_launch(void* const* d_in, const int* in_sizes, int n_in,
                              void* d_out, int out_size)
{
    const float* x     = (const float*)d_in[0];
    const float* Wq    = (const float*)d_in[1];
    const float* Wk    = (const float*)d_in[2];
    const float* Wv    = (const float*)d_in[3];
    const float* Wo    = (const float*)d_in[4];
    const float* gamma = (const float*)d_in[5];
    const float* beta  = (const float*)d_in[6];
    float* out = (float*)d_out;

    const int SM1 = (128*130 + 128*64) * 4;
    const int SM3 = (128*130 + 128*65) * 4;

    cudaFuncSetAttribute(k_qkv,  cudaFuncAttributeMaxDynamicSharedMemorySize, SM1);
    cudaFuncSetAttribute(k_attn, cudaFuncAttributeMaxDynamicSharedMemorySize, SM_ATTN);
    cudaFuncSetAttribute(k_proj, cudaFuncAttributeMaxDynamicSharedMemorySize, SM3);

    k_qkv <<<dim3(NSP/TN, BATCH, 3),      256, SM1>>>(x, Wq, Wk, Wv);
    k_attn<<<dim3(NSP/TQ, BATCH, KSPLIT), 256, SM_ATTN>>>();
    k_proj<<<dim3(NSP/TN, BATCH),         256, SM3>>>(x, Wo);
    k_norm<<<(BATCH*CH*NSP)/(4*256), 256>>>(gamma, beta, out);
}

// round 16
// speedup vs baseline: 1.0695x; 1.0695x over previous
#include <cuda_runtime.h>
#include <cuda_bf16.h>
#include <cuda_fp16.h>
#include <math_constants.h>
#include <cstdint>

#define BATCH 2
#define CH    128
#define NSP   4096
#define GROUPS 8
#define TN    64
#define EPSV  1e-5f

// attention tiling: 64 queries per CTA, 4 warps, 2 CTAs/SM
#define TQ     64
#define TKK    64
#define KSPLIT 2
#define NT2    (NSP/KSPLIT/TKK)   // 32

// ---------------- scratch (static __device__, allocation-free) ----------------
__device__ uint32_t g_Q16[BATCH*NSP*64];      // [b][n][cw] fp16x2
__device__ uint32_t g_K16[BATCH*NSP*64];      // [b][m][cw] fp16x2
__device__ uint32_t g_V16[BATCH*NSP*64];      // [b][m][cw] fp16x2 (row-major V)
__device__ float g_Op[KSPLIT*BATCH*NSP*CH];   // unnormalized O  [s][b][n][c]
__device__ float g_lp[KSPLIT*BATCH*NSP];      // exp-sums        [s][b][n]
__device__ float g_mx[KSPLIT*BATCH*NSP];      // row maxes       [s][b][n]
__device__ float g_Y [BATCH*CH*NSP];
__device__ float g_part [BATCH*64*GROUPS*2];

// ---------------- f32x2 helpers ----------------
__device__ __forceinline__ unsigned long long pk2(float x, float y){
    unsigned long long r; asm("mov.b64 %0, {%1,%2};" : "=l"(r) : "f"(x), "f"(y)); return r;
}
__device__ __forceinline__ void upk2(unsigned long long v, float& x, float& y){
    asm("mov.b64 {%0,%1}, %2;" : "=f"(x), "=f"(y) : "l"(v));
}
__device__ __forceinline__ void ffma2(unsigned long long& d, unsigned long long a, unsigned long long b){
    asm("fma.rn.f32x2 %0, %1, %2, %0;" : "+l"(d) : "l"(a), "l"(b));
}

// ---------------- smem / mma / ldmatrix / cp.async helpers ----------------
__device__ __forceinline__ uint32_t smem_u32(const void* p){
    uint32_t a;
    asm("{ .reg .u64 t; cvta.to.shared.u64 t, %1; cvt.u32.u64 %0, t; }" : "=r"(a) : "l"(p));
    return a;
}
__device__ __forceinline__ void cpa(uint32_t saddr, const void* g){
    asm volatile("cp.async.ca.shared.global [%0], [%1], 16;" :: "r"(saddr), "l"(g) : "memory");
}
#define CPA_COMMIT() asm volatile("cp.async.commit_group;" ::: "memory")
#define CPA_WAIT0()  asm volatile("cp.async.wait_group 0;" ::: "memory")
#define CPA_WAIT1()  asm volatile("cp.async.wait_group 1;" ::: "memory")

__device__ __forceinline__ void ldsm4(uint32_t a, uint32_t r[4]){
    asm volatile("ldmatrix.sync.aligned.m8n8.x4.shared.b16 {%0,%1,%2,%3}, [%4];"
      : "=r"(r[0]), "=r"(r[1]), "=r"(r[2]), "=r"(r[3]) : "r"(a));
}
__device__ __forceinline__ void ldsm4t(uint32_t a, uint32_t r[4]){
    asm volatile("ldmatrix.sync.aligned.m8n8.x4.trans.shared.b16 {%0,%1,%2,%3}, [%4];"
      : "=r"(r[0]), "=r"(r[1]), "=r"(r[2]), "=r"(r[3]) : "r"(a));
}
// fp16 mma
__device__ __forceinline__ void mmah(float c[4], const uint32_t a[4], const uint32_t b[2]){
    asm volatile("mma.sync.aligned.m16n8k16.row.col.f32.f16.f16.f32 "
      "{%0,%1,%2,%3}, {%4,%5,%6,%7}, {%8,%9}, {%0,%1,%2,%3};"
      : "+f"(c[0]), "+f"(c[1]), "+f"(c[2]), "+f"(c[3])
      : "r"(a[0]), "r"(a[1]), "r"(a[2]), "r"(a[3]), "r"(b[0]), "r"(b[1]));
}

// single fp16 pack of a float pair
__device__ __forceinline__ uint32_t packh2(float a, float b){
    __half2 h = __floats2half2_rn(a, b);
    return *reinterpret_cast<uint32_t*>(&h);
}

// smem byte offsets for k_attn (row stride 272B everywhere)
// Q: 64 rows.  K bufs: 64 rows x2.  V bufs: 64 rows x2.   total 87040 B
#define QS   0
#define KB0  17408
#define KBSZ 17408
#define VB0  52224
#define VBSZ 17408
#define SM_ATTN 87040

// ============================================================================
// K1: Q/K/V projections (fp32 scalar), direct register->global fp16 stores.
// All three -> single fp16 [b][row][c].
// ============================================================================
__global__ __launch_bounds__(256) void k_qkv(const float* __restrict__ x,
                                             const float* __restrict__ Wq,
                                             const float* __restrict__ Wk,
                                             const float* __restrict__ Wv)
{
    extern __shared__ float sm[];
    float* Wt = sm;               // [c][130]
    float* Xs = sm + 128*130;     // [c][64]

    const int n0  = blockIdx.x * TN;
    const int b   = blockIdx.y;
    const int z   = blockIdx.z;
    const float* W = (z == 0) ? Wq : ((z == 1) ? Wk : Wv);

    const int tid = threadIdx.x;
    const int tx  = tid & 15;
    const int ty  = tid >> 4;

    for (int idx = tid; idx < 128*64; idx += 256){
        int o  = idx >> 6;
        int cq = (idx & 63) << 1;
        float2 w = *(const float2*)(W + o*128 + cq);
        Wt[ cq   *130 + o] = w.x;
        Wt[(cq+1)*130 + o] = w.y;
    }
    const float* xb = x + (size_t)b*CH*NSP + n0;
    for (int idx = tid; idx < 128*16; idx += 256){
        int c = idx >> 4, u = (idx & 15) << 2;
        *(float4*)(Xs + c*64 + u) = *(const float4*)(xb + c*NSP + u);
    }
    __syncthreads();

    unsigned long long acc[4][4];
    #pragma unroll
    for (int i = 0; i < 4; i++)
        #pragma unroll
        for (int j = 0; j < 4; j++) acc[i][j] = 0ull;

    #pragma unroll 4
    for (int c = 0; c < 128; c++){
        unsigned long long wv[4]; float xn[4];
        #pragma unroll
        for (int j = 0; j < 4; j++)
            wv[j] = *(const unsigned long long*)(Wt + c*130 + 2*tx + 32*j);
        #pragma unroll
        for (int i = 0; i < 4; i++) xn[i] = Xs[c*64 + ty + 16*i];
        #pragma unroll
        for (int i = 0; i < 4; i++){
            unsigned long long xd = pk2(xn[i], xn[i]);
            #pragma unroll
            for (int j = 0; j < 4; j++) ffma2(acc[i][j], wv[j], xd);
        }
    }

    // direct stores: thread holds (o, o+1) pair = one fp16x2 word at [n][cw]
    uint32_t* ok = (z == 0 ? g_Q16 : (z == 1 ? g_K16 : g_V16)) + ((size_t)b*NSP + n0)*64;
    #pragma unroll
    for (int i = 0; i < 4; i++)
        #pragma unroll
        for (int j = 0; j < 4; j++){
            float a, bv; upk2(acc[i][j], a, bv);
            int n = ty + 16*i, cw = tx + 16*j;
            ok[n*64 + cw] = packh2(a, bv);
        }
}

// ============================================================================
// K2: HMMA flash attention, online softmax, split-K.
// TQ=64, 4 warps, 2 CTAs/SM: co-resident CTA fills tensor-pipe bubbles.
// QK^T: fp16 1-pass.  PV^T: fp16 1-pass (V via ldsm.trans).
// TK=64 tiles, double-buffered K and V, one __syncthreads per tile.
// ============================================================================
__global__ __launch_bounds__(128, 2) void k_attn()
{
    extern __shared__ char smc[];
    const uint32_t sb = smem_u32(smc);
    const int tid = threadIdx.x;
    const int wid = tid >> 5, lane = tid & 31;
    const int n0 = blockIdx.x * TQ;
    const int b  = blockIdx.y;
    const int sp = blockIdx.z;
    const int m_base = sp * (NSP/KSPLIT);

    const uint32_t* Q16 = g_Q16 + ((size_t)b*NSP + n0)*64;
    const uint32_t* K16 = g_K16 + (size_t)b*NSP*64;
    const uint32_t* V16 = g_V16 + (size_t)b*NSP*64;

    // ---- prologue group 0: Q + K(0) into K buf 0 ----
    for (int i = tid; i < 1024; i += 128){
        int r = i >> 4, q = i & 15;
        cpa(sb + QS + (uint32_t)r*272 + q*16, Q16 + r*64 + q*4);
    }
    for (int i = tid; i < 1024; i += 128){
        int r = i >> 4, q = i & 15;
        cpa(sb + KB0 + (uint32_t)r*272 + q*16, K16 + (size_t)(m_base + r)*64 + q*4);
    }
    CPA_COMMIT();
    // ---- prologue group 1: V(0) into V buf 0 ----
    for (int i = tid; i < 1024; i += 128){
        int r = i >> 4, q = i & 15;
        cpa(sb + VB0 + (uint32_t)r*272 + q*16, V16 + (size_t)(m_base + r)*64 + q*4);
    }
    CPA_COMMIT();
    CPA_WAIT1();            // Q + K(0) ready (V(0) may still fly)
    __syncthreads();

    // fragment address bases (row stride 272B everywhere)
    const int arow = 16*wid + (lane & 7) + ((lane >> 3) & 1)*8;
    const uint32_t aoff = (uint32_t)arow*272 + ((lane >> 4) & 1)*16;
    // K (non-trans): rows = n-dim via bit4; byte window = k-dim via bit3
    const int brow = (lane & 7) + ((lane >> 4) & 1)*8;
    const uint32_t boff = ((lane >> 3) & 1)*16;
    // V (trans): rows = k-dim via bit3; byte window = n-dim via bit4
    const int vrow = (lane & 7) + ((lane >> 3) & 1)*8;
    const uint32_t voff = ((lane >> 4) & 1)*16;

    // ---- cache Q A-fragments for the whole kernel ----
    uint32_t qf[8][4];
    #pragma unroll
    for (int k = 0; k < 8; k++) ldsm4(sb + QS + aoff + k*32, qf[k]);

    float oacc[16][4];
    #pragma unroll
    for (int i = 0; i < 16; i++)
        #pragma unroll
        for (int j = 0; j < 4; j++) oacc[i][j] = 0.f;
    float lsum0 = 0.f, lsum1 = 0.f;
    float mrow0 = -CUDART_INF_F, mrow1 = -CUDART_INF_F;

    for (int t = 0; t < NT2; t++){
        const uint32_t kb = sb + KB0 + (uint32_t)(t & 1)*KBSZ;
        const uint32_t vb = sb + VB0 + (uint32_t)(t & 1)*VBSZ;

        // tile barrier; confirm K(t) landed (pending <= {V(t)})
        __syncthreads();
        CPA_WAIT1();

        // earliest possible K(t+1) prefetch (writes other K buf)
        if (t + 1 < NT2){
            const int m1 = m_base + (t + 1)*TKK;
            const uint32_t kn = sb + KB0 + (uint32_t)((t + 1) & 1)*KBSZ;
            for (int i = tid; i < 1024; i += 128){
                int r = i >> 4, q = i & 15;
                cpa(kn + (uint32_t)r*272 + q*16, K16 + (size_t)(m1 + r)*64 + q*4);
            }
            CPA_COMMIT();
        }

        // ---- S = Q K^T : fp16, 1 pass, B loaded once per (k,jj) ----
        float sacc[8][4];
        #pragma unroll
        for (int i = 0; i < 8; i++)
            #pragma unroll
            for (int j = 0; j < 4; j++) sacc[i][j] = 0.f;

        #pragma unroll
        for (int k = 0; k < 8; k++){
            #pragma unroll
            for (int jj = 0; jj < 4; jj++){
                uint32_t bh[4];
                uint32_t ro = (uint32_t)(16*jj + brow)*272 + boff + k*32;
                ldsm4(kb + ro, bh);
                mmah(sacc[2*jj],     qf[k], bh);
                mmah(sacc[2*jj + 1], qf[k], bh + 2);
            }
        }

        // ---- online row max over this tile (rows g and g+8 of the quad) ----
        float tm0 = sacc[0][0], tm1 = sacc[0][2];
        #pragma unroll
        for (int j = 0; j < 8; j++){
            tm0 = fmaxf(tm0, fmaxf(sacc[j][0], sacc[j][1]));
            tm1 = fmaxf(tm1, fmaxf(sacc[j][2], sacc[j][3]));
        }
        #pragma unroll
        for (int d = 1; d < 4; d <<= 1){
            tm0 = fmaxf(tm0, __shfl_xor_sync(0xffffffffu, tm0, d));
            tm1 = fmaxf(tm1, __shfl_xor_sync(0xffffffffu, tm1, d));
        }
        float mn0 = fmaxf(mrow0, tm0), mn1 = fmaxf(mrow1, tm1);
        float sc0 = __expf(mrow0 - mn0), sc1 = __expf(mrow1 - mn1);
        mrow0 = mn0; mrow1 = mn1;
        if (!__all_sync(0xffffffffu, (sc0 == 1.0f) && (sc1 == 1.0f))){
            #pragma unroll
            for (int i = 0; i < 16; i++){
                oacc[i][0] *= sc0; oacc[i][1] *= sc0;
                oacc[i][2] *= sc1; oacc[i][3] *= sc1;
            }
            lsum0 *= sc0; lsum1 *= sc1;
        }

        // ---- P = exp(S - m_row); pack into SINGLE fp16 A-fragments ----
        uint32_t pf[4][4];
        #pragma unroll
        for (int j = 0; j < 8; j++){
            float p0 = __expf(sacc[j][0] - mn0);
            float p1 = __expf(sacc[j][1] - mn0);
            float p2 = __expf(sacc[j][2] - mn1);
            float p3 = __expf(sacc[j][3] - mn1);
            lsum0 += p0 + p1; lsum1 += p2 + p3;
            int jk = j >> 1, hv = (j & 1) << 1;
            pf[jk][hv]     = packh2(p0, p1);
            pf[jk][hv + 1] = packh2(p2, p3);
        }

        // V(t) ready?  pending: {V(t), K(t+1)} -> wait 1;  last tile: wait 0
        if (t + 1 < NT2) { CPA_WAIT1(); } else { CPA_WAIT0(); }

        // earliest possible V(t+1) prefetch
        if (t + 1 < NT2){
            const int m1 = m_base + (t + 1)*TKK;
            const uint32_t vn = sb + VB0 + (uint32_t)((t + 1) & 1)*VBSZ;
            for (int i = tid; i < 1024; i += 128){
                int r = i >> 4, q = i & 15;
                cpa(vn + (uint32_t)r*272 + q*16, V16 + (size_t)(m1 + r)*64 + q*4);
            }
            CPA_COMMIT();
        }

        // ---- O += P V^T : fp16 1 pass, V [m][c] via ldsm.trans ----
        #pragma unroll
        for (int k = 0; k < 4; k++){
            #pragma unroll
            for (int jj = 0; jj < 8; jj++){
                uint32_t bh[4];
                uint32_t ro = (uint32_t)(16*k + vrow)*272 + voff + jj*32;
                ldsm4t(vb + ro, bh);
                mmah(oacc[2*jj],     pf[k], bh);
                mmah(oacc[2*jj + 1], pf[k], bh + 2);
            }
        }
    }

    // ---- epilogue: l and m per row, unnormalized (max-relative) O out ----
    #pragma unroll
    for (int d = 1; d < 4; d <<= 1){
        lsum0 += __shfl_xor_sync(0xffffffffu, lsum0, d);
        lsum1 += __shfl_xor_sync(0xffffffffu, lsum1, d);
    }
    const int g = lane >> 2, q = lane & 3;
    const int row = 16*wid + g;
    if (q == 0){
        size_t lb = ((size_t)sp*BATCH + b)*NSP + n0;
        g_lp[lb + row]     = lsum0;
        g_lp[lb + row + 8] = lsum1;
        g_mx[lb + row]     = mrow0;
        g_mx[lb + row + 8] = mrow1;
    }
    float* Ob = g_Op + (((size_t)sp*BATCH + b)*NSP + n0)*CH;
    #pragma unroll
    for (int tt = 0; tt < 16; tt++){
        int c = 8*tt + 2*q;
        *(float2*)(Ob + (size_t)row*CH + c)       = make_float2(oacc[tt][0], oacc[tt][1]);
        *(float2*)(Ob + (size_t)(row + 8)*CH + c) = make_float2(oacc[tt][2], oacc[tt][3]);
    }
}

// ============================================================================
// K3: combine splits (m/l merge), y = x + Wo @ h, per-(b,group) partials.
// ============================================================================
__global__ __launch_bounds__(256) void k_proj(const float* __restrict__ x,
                                              const float* __restrict__ Wo)
{
    extern __shared__ float sm[];
    __shared__ float w0S[64], w1S[64];
    float* Wt = sm;               // [c][130]
    float* HS = sm + 128*130;     // [n][129] compute; [o][65] staging

    const int n0 = blockIdx.x * TN;
    const int b  = blockIdx.y;
    const int tid = threadIdx.x;
    const int tx  = tid & 15;
    const int ty  = tid >> 4;

    if (tid < 64){
        size_t i0 = ((size_t)0*BATCH + b)*NSP + n0 + tid;
        size_t i1 = ((size_t)1*BATCH + b)*NSP + n0 + tid;
        float l0 = g_lp[i0], l1 = g_lp[i1];
        float m0 = g_mx[i0], m1 = g_mx[i1];
        float M  = fmaxf(m0, m1);
        float e0 = __expf(m0 - M), e1 = __expf(m1 - M);
        float rl = 1.0f / (l0*e0 + l1*e1);
        w0S[tid] = e0 * rl;
        w1S[tid] = e1 * rl;
    }
    for (int idx = tid; idx < 128*64; idx += 256){
        int o  = idx >> 6;
        int cq = (idx & 63) << 1;
        float2 w = *(const float2*)(Wo + o*128 + cq);
        Wt[ cq   *130 + o] = w.x;
        Wt[(cq+1)*130 + o] = w.y;
    }
    __syncthreads();

    const float* O0 = g_Op + (((size_t)0*BATCH + b)*NSP + n0)*CH;
    const float* O1 = g_Op + (((size_t)1*BATCH + b)*NSP + n0)*CH;
    for (int idx = tid; idx < 64*128; idx += 256){
        int n = idx >> 7, c = idx & 127;
        HS[n*129 + c] = O0[idx]*w0S[n] + O1[idx]*w1S[n];
    }
    __syncthreads();

    unsigned long long acc[4][4];
    #pragma unroll
    for (int i = 0; i < 4; i++)
        #pragma unroll
        for (int j = 0; j < 4; j++) acc[i][j] = 0ull;

    #pragma unroll 4
    for (int c = 0; c < 128; c++){
        unsigned long long wv[4]; float hv[4];
        #pragma unroll
        for (int j = 0; j < 4; j++)
            wv[j] = *(const unsigned long long*)(Wt + c*130 + 2*tx + 32*j);
        #pragma unroll
        for (int i = 0; i < 4; i++) hv[i] = HS[(ty + 16*i)*129 + c];
        #pragma unroll
        for (int i = 0; i < 4; i++){
            unsigned long long hd = pk2(hv[i], hv[i]);
            #pragma unroll
            for (int j = 0; j < 4; j++) ffma2(acc[i][j], wv[j], hd);
        }
    }
    __syncthreads();

    float* St = HS;  // [o][65]
    #pragma unroll
    for (int i = 0; i < 4; i++)
        #pragma unroll
        for (int j = 0; j < 4; j++){
            float a, bv; upk2(acc[i][j], a, bv);
            int o = 2*tx + 32*j, n = ty + 16*i;
            St[ o   *65 + n] = a;
            St[(o+1)*65 + n] = bv;
        }
    __syncthreads();

    const float* xb = x   + (size_t)b*CH*NSP + n0;
    float*       yb = g_Y + (size_t)b*CH*NSP + n0;
    const int w = tid >> 5, lane = tid & 31;
    float s1 = 0.f, s2 = 0.f;
    for (int k = 0; k < 32; k++){
        int e = w*1024 + k*32 + lane;
        int o = e >> 6, n = e & 63;
        float val = xb[o*NSP + n] + St[o*65 + n];
        yb[o*NSP + n] = val;
        s1 += val; s2 += val*val;
    }
    #pragma unroll
    for (int d = 16; d >= 1; d >>= 1){
        s1 += __shfl_xor_sync(0xffffffffu, s1, d);
        s2 += __shfl_xor_sync(0xffffffffu, s2, d);
    }
    if (lane == 0){
        float* p = g_part + ((size_t)(b*64 + blockIdx.x)*GROUPS + w)*2;
        p[0] = s1; p[1] = s2;
    }
}

// K4: GroupNorm + affine + SiLU, with fused (redundant, deterministic)
// per-block reduction of the 64 partial sums for this block's group.
__global__ __launch_bounds__(256) void k_norm(const float* __restrict__ gamma,
                                              const float* __restrict__ beta,
                                              float* __restrict__ out)
{
    __shared__ float sh_mean, sh_inv;
    const int tid = threadIdx.x;
    const int e0 = blockIdx.x << 10;        // 1024 elems per block
    const int b = e0 >> 19;
    const int c = (e0 >> 12) & 127;
    const int g = c >> 4;

    if (tid < 32){
        const float* p = g_part + ((size_t)(b*64)*GROUPS + g)*2;
        float s1 = p[(size_t)tid*GROUPS*2]     + p[(size_t)(tid+32)*GROUPS*2];
        float s2 = p[(size_t)tid*GROUPS*2 + 1] + p[(size_t)(tid+32)*GROUPS*2 + 1];
        #pragma unroll
        for (int d = 16; d >= 1; d >>= 1){
            s1 += __shfl_xor_sync(0xffffffffu, s1, d);
            s2 += __shfl_xor_sync(0xffffffffu, s2, d);
        }
        if (tid == 0){
            const float icnt = 1.0f / 65536.0f;
            float mean = s1 * icnt;
            float var  = s2 * icnt - mean*mean;
            sh_mean = mean;
            sh_inv  = rsqrtf(var + EPSV);
        }
    }
    __syncthreads();

    const float mean = sh_mean, inv = sh_inv;
    const float ga = gamma[c], be = beta[c];
    const int e = e0 + tid*4;
    float4 y = *(const float4*)(g_Y + e);
    float4 r;
    float t = (y.x - mean)*inv*ga + be; r.x = t / (1.0f + __expf(-t));
    t = (y.y - mean)*inv*ga + be;       r.y = t / (1.0f + __expf(-t));
    t = (y.z - mean)*inv*ga + be;       r.z = t / (1.0f + __expf(-t));
    t = (y.w - mean)*inv*ga + be;       r.w = t / (1.0f + __expf(-t));
    *(float4*)(out + e) = r;
}

// ============================================================================
extern "C" void kernel_launch(void* const* d_in, const int* in_sizes, int n_in,
                              void* d_out, int out_size)
{
    const float* x     = (const float*)d_in[0];
    const float* Wq    = (const float*)d_in[1];
    const float* Wk    = (const float*)d_in[2];
    const float* Wv    = (const float*)d_in[3];
    const float* Wo    = (const float*)d_in[4];
    const float* gamma = (const float*)d_in[5];
    const float* beta  = (const float*)d_in[6];
    float* out = (float*)d_out;

    const int SM1 = (128*130 + 128*64) * 4;
    const int SM3 = (128*130 + 128*65) * 4;

    cudaFuncSetAttribute(k_qkv,  cudaFuncAttributeMaxDynamicSharedMemorySize, SM1);
    cudaFuncSetAttribute(k_attn, cudaFuncAttributeMaxDynamicSharedMemorySize, SM_ATTN);
    cudaFuncSetAttribute(k_proj, cudaFuncAttributeMaxDynamicSharedMemorySize, SM3);

    k_qkv <<<dim3(NSP/TN, BATCH, 3),      256, SM1>>>(x, Wq, Wk, Wv);
    k_attn<<<dim3(NSP/TQ, BATCH, KSPLIT), 128, SM_ATTN>>>();
    k_proj<<<dim3(NSP/TN, BATCH),         256, SM3>>>(x, Wo);
    k_norm<<<(BATCH*CH*NSP)/(4*256), 256>>>(gamma, beta, out);
}